// round 13
// baseline (speedup 1.0000x reference)
#include <cuda_runtime.h>
#include <cuda_bf16.h>
#include <cstdint>

// Problem constants
#define NB    4
#define NC    256
#define HW    4096
#define NCOLS 16384          // B*H*W
#define MW    320            // 64 attn channels + 256 hv channels

// -------- persistent device scratch (allocation-free rule) --------
__device__ float g_constz[NC];                            // folded bias [256]
__device__ float g_G[(size_t)MW * NCOLS];                 // stage1: rows 0..63 = exp(attn), rows 64.. = hv
__device__ __nv_bfloat16 g_W1hi[MW * NC];                 // folded weights hi [320][256]
__device__ __nv_bfloat16 g_W1lo[MW * NC];                 // folded weights lo
__device__ __nv_bfloat16 g_Yhi[(size_t)NCOLS * 1024];     // stage2 out hi  [16384][1024]
__device__ __nv_bfloat16 g_Ylo[(size_t)NCOLS * 1024];     // stage2 out lo
__device__ __nv_bfloat16 g_QWhi[256 * 1024];              // q_w hi
__device__ __nv_bfloat16 g_QWlo[256 * 1024];              // q_w lo

// ======================= portable PTX helpers (sm_80+ ISA only) =======================
__device__ __forceinline__ uint32_t smem_u32(const void* p) {
    return (uint32_t)__cvta_generic_to_shared(p);
}
__device__ __forceinline__ void cp16(uint32_t s, const void* g) {
    asm volatile("cp.async.cg.shared.global [%0], [%1], 16;" :: "r"(s), "l"(g));
}
__device__ __forceinline__ void cp_commit() {
    asm volatile("cp.async.commit_group;" ::: "memory");
}
template <int N> __device__ __forceinline__ void cp_wait() {
    asm volatile("cp.async.wait_group %0;" :: "n"(N) : "memory");
}
__device__ __forceinline__ void ldm_x4(uint32_t a, uint32_t& r0, uint32_t& r1,
                                       uint32_t& r2, uint32_t& r3) {
    asm volatile("ldmatrix.sync.aligned.m8n8.x4.shared.b16 {%0,%1,%2,%3}, [%4];"
                 : "=r"(r0), "=r"(r1), "=r"(r2), "=r"(r3) : "r"(a));
}
__device__ __forceinline__ void mma16816(float* d, const uint32_t* a, const uint32_t* b) {
    asm volatile("mma.sync.aligned.m16n8k16.row.col.f32.bf16.bf16.f32 "
                 "{%0,%1,%2,%3}, {%4,%5,%6,%7}, {%8,%9}, {%0,%1,%2,%3};"
                 : "+f"(d[0]), "+f"(d[1]), "+f"(d[2]), "+f"(d[3])
                 : "r"(a[0]), "r"(a[1]), "r"(a[2]), "r"(a[3]), "r"(b[0]), "r"(b[1]));
}

// ======================= precompute (tiny) =======================
__global__ void precompute_k(const float* __restrict__ kv_w,
                             const float* __restrict__ dot_w,
                             const float* __restrict__ head_w,
                             const float* __restrict__ head_b,
                             const float* __restrict__ q_w,
                             const float* __restrict__ q_b) {
    int i = blockIdx.x * blockDim.x + threadIdx.x;
    if (i < 64 * 256) {
        int m = i >> 8, c = i & 255;
        int n = m >> 4, q = m & 15;
        float s = 0.f;
        #pragma unroll 8
        for (int d = 0; d < 64; d++)
            s += dot_w[(n * 16 + q) * 64 + d] * kv_w[(n * 64 + d) * 256 + c];
        __nv_bfloat16 hi = __float2bfloat16(s);
        g_W1hi[m * 256 + c] = hi;
        g_W1lo[m * 256 + c] = __float2bfloat16(s - __bfloat162float(hi));
    } else if (i < 64 * 256 + 256 * 256) {
        int j = i - 64 * 256;
        int m = j >> 8, c = j & 255;
        int n = m >> 6, op = m & 63;
        float s = 0.f;
        #pragma unroll 8
        for (int d = 0; d < 64; d++)
            s += head_w[op * 256 + n * 64 + d] * kv_w[(256 + n * 64 + d) * 256 + c];
        __nv_bfloat16 hi = __float2bfloat16(s);
        g_W1hi[(64 + m) * 256 + c] = hi;
        g_W1lo[(64 + m) * 256 + c] = __float2bfloat16(s - __bfloat162float(hi));
    } else if (i < 64 * 256 + 256 * 256 + 256) {
        int o = i - (64 * 256 + 256 * 256);
        float s = q_b[o];
        for (int c = 0; c < 1024; c += 4) {
            float4 v = *reinterpret_cast<const float4*>(&q_w[o * 1024 + c]);
            int hb = c & 63;
            s += v.x * head_b[hb] + v.y * head_b[hb + 1]
               + v.z * head_b[hb + 2] + v.w * head_b[hb + 3];
        }
        g_constz[o] = s;
    } else if (i < 64 * 256 + 256 * 256 + 256 + 256 * 1024) {
        int j = i - (64 * 256 + 256 * 256 + 256);
        float v = q_w[j];
        __nv_bfloat16 hi = __float2bfloat16(v);
        g_QWhi[j] = hi;
        g_QWlo[j] = __float2bfloat16(v - __bfloat162float(hi));
    }
}

// ======================= K1: tensor-core bf16-split GEMM + fused exp =======================
#define C1_RS    80
#define C1_AHI   0
#define C1_ALO   25600
#define C1_BHI   51200
#define C1_BLO   56320
#define C1_STG   61440
#define C1_SMEM  78848

__device__ __forceinline__ void k1_issueA(uint32_t sb, int k0, int t) {
    #pragma unroll
    for (int i = 0; i < 5; ++i) {
        int idx = t + i * 256;
        int row = idx >> 2, c = idx & 3;
        uint32_t so = row * C1_RS + c * 16;
        size_t go = (size_t)row * 256 + k0 + c * 8;
        cp16(sb + C1_AHI + so, g_W1hi + go);
        cp16(sb + C1_ALO + so, g_W1lo + go);
    }
}
__device__ __forceinline__ void k1_issueStg(uint32_t sb, int buf, const float* __restrict__ xb,
                                            int col0, int k0, int t) {
    #pragma unroll
    for (int i = 0; i < 2; ++i) {
        int idx = t + i * 256;
        int row = idx >> 4, c = idx & 15;
        cp16(sb + C1_STG + buf * 8704 + row * 272 + c * 16,
             xb + (size_t)(k0 + row) * HW + col0 + c * 4);
    }
}

__global__ void __launch_bounds__(256, 2) k1_tc(const float* __restrict__ x) {
    extern __shared__ __align__(128) char smem[];
    const uint32_t sb = smem_u32(smem);
    const int t = threadIdx.x, wid = t >> 5, lid = t & 31;
    const int col0 = blockIdx.x * 64;
    const int b    = blockIdx.y;
    const int wm = (wid & 3) * 80, wn = (wid >> 2) * 32;
    const float* xb = x + (size_t)b * NC * HW;

    float acc[20][4];
    #pragma unroll
    for (int i = 0; i < 20; i++) { acc[i][0] = acc[i][1] = acc[i][2] = acc[i][3] = 0.f; }

    k1_issueA(sb, 0, t);
    k1_issueStg(sb, 0, xb, col0, 0, t);
    cp_commit();

    const uint32_t a_off = (uint32_t)((lid & 15) * C1_RS + (lid >> 4) * 16);
    const int bn = (lid & 7) + ((lid >> 4) << 3);
    const uint32_t b_off = (uint32_t)(bn * C1_RS + ((lid >> 3) & 1) * 16);
    const int cn = t & 63, ckq = t >> 6;

    for (int c = 0; c < 8; ++c) {
        if (c < 7) {
            k1_issueStg(sb, (c + 1) & 1, xb, col0, (c + 1) * 32, t);
            cp_commit();
            cp_wait<1>();
        } else {
            cp_wait<0>();
        }
        __syncthreads();
        {   // convert fp32 staging [k][n] -> bf16 hi/lo [n][k]
            const float* stg = reinterpret_cast<const float*>(smem + C1_STG + (c & 1) * 8704);
            unsigned short hh[8], ll[8];
            #pragma unroll
            for (int j = 0; j < 8; ++j) {
                float f = stg[(ckq * 8 + j) * 68 + cn];
                __nv_bfloat16 hi = __float2bfloat16(f);
                __nv_bfloat16 lo = __float2bfloat16(f - __bfloat162float(hi));
                hh[j] = __bfloat16_as_ushort(hi);
                ll[j] = __bfloat16_as_ushort(lo);
            }
            uint32_t base = cn * C1_RS + ckq * 16;
            *reinterpret_cast<uint4*>(smem + C1_BHI + base) =
                make_uint4((uint32_t)hh[0] | ((uint32_t)hh[1] << 16),
                           (uint32_t)hh[2] | ((uint32_t)hh[3] << 16),
                           (uint32_t)hh[4] | ((uint32_t)hh[5] << 16),
                           (uint32_t)hh[6] | ((uint32_t)hh[7] << 16));
            *reinterpret_cast<uint4*>(smem + C1_BLO + base) =
                make_uint4((uint32_t)ll[0] | ((uint32_t)ll[1] << 16),
                           (uint32_t)ll[2] | ((uint32_t)ll[3] << 16),
                           (uint32_t)ll[4] | ((uint32_t)ll[5] << 16),
                           (uint32_t)ll[6] | ((uint32_t)ll[7] << 16));
        }
        __syncthreads();
        const uint32_t ahib = sb + C1_AHI + wm * C1_RS;
        const uint32_t alob = sb + C1_ALO + wm * C1_RS;
        const uint32_t bhib = sb + C1_BHI + wn * C1_RS;
        const uint32_t blob = sb + C1_BLO + wn * C1_RS;
        #pragma unroll
        for (int kk = 0; kk < 2; ++kk) {
            uint32_t kb = kk * 32;
            uint32_t bh[8], bl[8];
            #pragma unroll
            for (int nb = 0; nb < 2; ++nb) {
                ldm_x4(bhib + nb * 16 * C1_RS + b_off + kb,
                       bh[nb * 4], bh[nb * 4 + 1], bh[nb * 4 + 2], bh[nb * 4 + 3]);
                ldm_x4(blob + nb * 16 * C1_RS + b_off + kb,
                       bl[nb * 4], bl[nb * 4 + 1], bl[nb * 4 + 2], bl[nb * 4 + 3]);
            }
            #pragma unroll
            for (int mi = 0; mi < 5; ++mi) {
                uint32_t ah[4], al[4];
                ldm_x4(ahib + mi * 16 * C1_RS + a_off + kb, ah[0], ah[1], ah[2], ah[3]);
                ldm_x4(alob + mi * 16 * C1_RS + a_off + kb, al[0], al[1], al[2], al[3]);
                #pragma unroll
                for (int nj = 0; nj < 4; ++nj) mma16816(acc[mi * 4 + nj], ah, bh + nj * 2);
                #pragma unroll
                for (int nj = 0; nj < 4; ++nj) mma16816(acc[mi * 4 + nj], al, bh + nj * 2);
                #pragma unroll
                for (int nj = 0; nj < 4; ++nj) mma16816(acc[mi * 4 + nj], ah, bl + nj * 2);
            }
        }
        __syncthreads();
        if (c < 7) {
            k1_issueA(sb, (c + 1) * 32, t);
            cp_commit();
        }
    }

    const int bcol = b * HW;
    #pragma unroll
    for (int mi = 0; mi < 5; ++mi) {
        int row = wm + mi * 16 + (lid >> 2);
        #pragma unroll
        for (int nj = 0; nj < 4; ++nj) {
            int col = bcol + col0 + wn + nj * 8 + (lid & 3) * 2;
            float* a = acc[mi * 4 + nj];
            float v0 = a[0], v1 = a[1], v2 = a[2], v3 = a[3];
            if (row < 64)     { v0 = __expf(v0); v1 = __expf(v1); }
            if (row + 8 < 64) { v2 = __expf(v2); v3 = __expf(v3); }
            *reinterpret_cast<float2*>(&g_G[(size_t)row * NCOLS + col]) = make_float2(v0, v1);
            *reinterpret_cast<float2*>(&g_G[(size_t)(row + 8) * NCOLS + col]) = make_float2(v2, v3);
        }
    }
}

// ======================= K2: windowed softmax (exp precomputed) + aggregation =======================
__global__ void __launch_bounds__(512, 2) k2_window() {
    __shared__ float sE[16][56];
    __shared__ float sHV[64][56];
    __shared__ float sSM[16][16][9];

    int t  = threadIdx.x;
    int w0 = blockIdx.x * 16;
    int h  = blockIdx.y;
    int b  = blockIdx.z;
    int bcol = b * HW;
    int px = t >> 5;
    int oh = t & 31;

    float acc0[16], acc1[16];
    #pragma unroll
    for (int q = 0; q < 16; q++) { acc0[q] = 0.f; acc1[q] = 0.f; }

    for (int n = 0; n < 4; n++) {
        __syncthreads();
        for (int i = t; i < 864; i += 512) {
            int q = i / 54, pos = i % 54;
            int r = pos / 18, cc = pos % 18;
            int gh = h - 1 + r, gw = w0 - 1 + cc;
            float v = 1.0f;
            if (gh >= 0 && gh < 64 && gw >= 0 && gw < 64)
                v = g_G[(size_t)(n * 16 + q) * NCOLS + bcol + gh * 64 + gw];
            sE[q][pos] = v;
        }
        for (int i = t; i < 3456; i += 512) {
            int ch = i / 54, pos = i % 54;
            int r = pos / 18, cc = pos % 18;
            int gh = h - 1 + r, gw = w0 - 1 + cc;
            float v = 0.f;
            if (gh >= 0 && gh < 64 && gw >= 0 && gw < 64)
                v = g_G[(size_t)(64 + n * 64 + ch) * NCOLS + bcol + gh * 64 + gw];
            sHV[ch][pos] = v;
        }
        __syncthreads();
        if (t < 256) {
            int p2 = t >> 4, q = t & 15;
            float e[9], s = 0.f;
            #pragma unroll
            for (int r = 0; r < 3; r++)
                #pragma unroll
                for (int dc = 0; dc < 3; dc++) {
                    float v = sE[q][r * 18 + p2 + dc];
                    e[r * 3 + dc] = v; s += v;
                }
            float rs = 1.0f / s;
            #pragma unroll
            for (int l = 0; l < 9; l++) sSM[p2][q][l] = e[l] * rs;
        }
        __syncthreads();
        #pragma unroll
        for (int r = 0; r < 3; r++) {
            float h0a = sHV[oh][r * 18 + px],      h0b = sHV[oh][r * 18 + px + 1],
                  h0c = sHV[oh][r * 18 + px + 2];
            float h1a = sHV[oh + 32][r * 18 + px], h1b = sHV[oh + 32][r * 18 + px + 1],
                  h1c = sHV[oh + 32][r * 18 + px + 2];
            #pragma unroll
            for (int q = 0; q < 16; q++) {
                float s0 = sSM[px][q][r * 3 + 0];
                float s1 = sSM[px][q][r * 3 + 1];
                float s2 = sSM[px][q][r * 3 + 2];
                acc0[q] += s0 * h0a + s1 * h0b + s2 * h0c;
                acc1[q] += s0 * h1a + s1 * h1b + s2 * h1c;
            }
        }
    }
    size_t col = (size_t)bcol + h * 64 + w0 + px;
    __nv_bfloat16* yh = g_Yhi + col * 1024 + oh;
    __nv_bfloat16* yl = g_Ylo + col * 1024 + oh;
    #pragma unroll
    for (int q = 0; q < 16; q++) {
        float v0 = acc0[q];
        __nv_bfloat16 h0 = __float2bfloat16(v0);
        yh[q * 64] = h0;
        yl[q * 64] = __float2bfloat16(v0 - __bfloat162float(h0));
        float v1 = acc1[q];
        __nv_bfloat16 h1 = __float2bfloat16(v1);
        yh[q * 64 + 32] = h1;
        yl[q * 64 + 32] = __float2bfloat16(v1 - __bfloat162float(h1));
    }
}

// ======================= K3: mma.sync bf16-split GEMM =======================
#define K3_RS    80
#define K3_TILE  10240
#define K3_STAGE 40960
#define K3_SMEM  81920

__device__ __forceinline__ void k3_issue(uint32_t sbuf,
                                         const __nv_bfloat16* __restrict__ A0,
                                         const __nv_bfloat16* __restrict__ A1,
                                         const __nv_bfloat16* __restrict__ B0,
                                         const __nv_bfloat16* __restrict__ B1,
                                         int k0, int t) {
    int r = t >> 2, c = t & 3;
    #pragma unroll
    for (int half = 0; half < 2; ++half) {
        int row = r + half * 64;
        uint32_t so = row * K3_RS + c * 16;
        size_t go = (size_t)row * 1024 + k0 + c * 8;
        cp16(sbuf + so,                A0 + go);
        cp16(sbuf + K3_TILE + so,      A1 + go);
        cp16(sbuf + 2 * K3_TILE + so,  B0 + go);
        cp16(sbuf + 3 * K3_TILE + so,  B1 + go);
    }
}

__global__ void __launch_bounds__(256, 2) k3_mma(float* __restrict__ out) {
    extern __shared__ __align__(128) char smem[];
    const uint32_t sb = smem_u32(smem);
    const int t = threadIdx.x, wid = t >> 5, lid = t & 31;
    const int m0 = blockIdx.y * 128, n0 = blockIdx.x * 128;
    const int wm = (wid & 3) * 32, wn = (wid >> 2) * 64;

    const __nv_bfloat16* Ah = g_QWhi + (size_t)m0 * 1024;
    const __nv_bfloat16* Al = g_QWlo + (size_t)m0 * 1024;
    const __nv_bfloat16* Bh = g_Yhi + (size_t)n0 * 1024;
    const __nv_bfloat16* Bl = g_Ylo + (size_t)n0 * 1024;

    float acc[16][4];
    #pragma unroll
    for (int i = 0; i < 16; i++) { acc[i][0] = acc[i][1] = acc[i][2] = acc[i][3] = 0.f; }

    k3_issue(sb, Ah, Al, Bh, Bl, 0, t);
    cp_commit();

    const uint32_t a_off = (uint32_t)((lid & 15) * K3_RS + (lid >> 4) * 16);
    const int bn = (lid & 7) + ((lid >> 4) << 3);
    const uint32_t b_off = (uint32_t)(bn * K3_RS + ((lid >> 3) & 1) * 16);

    for (int cs = 0; cs < 32; ++cs) {
        if (cs < 31) {
            k3_issue(sb + ((cs + 1) & 1) * K3_STAGE, Ah, Al, Bh, Bl, (cs + 1) * 32, t);
            cp_commit();
            cp_wait<1>();
        } else {
            cp_wait<0>();
        }
        __syncthreads();
        uint32_t buf   = sb + (cs & 1) * K3_STAGE;
        uint32_t abase = buf + wm * K3_RS;
        uint32_t bbase = buf + 2 * K3_TILE + wn * K3_RS;
        #pragma unroll
        for (int kk = 0; kk < 2; ++kk) {
            uint32_t kb = kk * 32;
            uint32_t ah[8], al[8], bb[16];
            ldm_x4(abase + a_off + kb,                           ah[0], ah[1], ah[2], ah[3]);
            ldm_x4(abase + 16 * K3_RS + a_off + kb,              ah[4], ah[5], ah[6], ah[7]);
            ldm_x4(abase + K3_TILE + a_off + kb,                 al[0], al[1], al[2], al[3]);
            ldm_x4(abase + K3_TILE + 16 * K3_RS + a_off + kb,    al[4], al[5], al[6], al[7]);
            #pragma unroll
            for (int nb = 0; nb < 4; ++nb)
                ldm_x4(bbase + nb * 16 * K3_RS + b_off + kb,
                       bb[nb * 4], bb[nb * 4 + 1], bb[nb * 4 + 2], bb[nb * 4 + 3]);
            #pragma unroll
            for (int nj = 0; nj < 8; ++nj)
                #pragma unroll
                for (int mi = 0; mi < 2; ++mi)
                    mma16816(acc[mi * 8 + nj], ah + mi * 4, bb + nj * 2);   // hi*hi
            #pragma unroll
            for (int nj = 0; nj < 8; ++nj)
                #pragma unroll
                for (int mi = 0; mi < 2; ++mi)
                    mma16816(acc[mi * 8 + nj], al + mi * 4, bb + nj * 2);   // lo*hi
            #pragma unroll
            for (int nb = 0; nb < 4; ++nb)
                ldm_x4(bbase + K3_TILE + nb * 16 * K3_RS + b_off + kb,
                       bb[nb * 4], bb[nb * 4 + 1], bb[nb * 4 + 2], bb[nb * 4 + 3]);
            #pragma unroll
            for (int nj = 0; nj < 8; ++nj)
                #pragma unroll
                for (int mi = 0; mi < 2; ++mi)
                    mma16816(acc[mi * 8 + nj], ah + mi * 4, bb + nj * 2);   // hi*lo
        }
        __syncthreads();
    }

    const int bidx = blockIdx.x >> 5;
    const int hwb  = ((blockIdx.x & 31) * 128) + wn + (lid & 3) * 2;
    #pragma unroll
    for (int mi = 0; mi < 2; ++mi) {
        int row = m0 + wm + mi * 16 + (lid >> 2);
        float cz0 = g_constz[row], cz1 = g_constz[row + 8];
        float* p0 = out + (size_t)bidx * 1048576 + (size_t)row * 4096 + hwb;
        float* p1 = p0 + 8 * 4096;
        #pragma unroll
        for (int nj = 0; nj < 8; ++nj) {
            float* a = acc[mi * 8 + nj];
            *reinterpret_cast<float2*>(p0 + nj * 8) = make_float2(a[0] + cz0, a[1] + cz0);
            *reinterpret_cast<float2*>(p1 + nj * 8) = make_float2(a[2] + cz1, a[3] + cz1);
        }
    }
}

// ======================= launch =======================
extern "C" void kernel_launch(void* const* d_in, const int* in_sizes, int n_in,
                              void* d_out, int out_size) {
    (void)in_sizes; (void)n_in; (void)out_size;
    const float* x      = (const float*)d_in[0];
    const float* kv_w   = (const float*)d_in[1];
    const float* dot_w  = (const float*)d_in[2];
    const float* head_w = (const float*)d_in[3];
    const float* head_b = (const float*)d_in[4];
    const float* q_w    = (const float*)d_in[5];
    const float* q_b    = (const float*)d_in[6];
    float* out = (float*)d_out;

    cudaFuncSetAttribute(k1_tc,  cudaFuncAttributeMaxDynamicSharedMemorySize, C1_SMEM);
    cudaFuncSetAttribute(k3_mma, cudaFuncAttributeMaxDynamicSharedMemorySize, K3_SMEM);

    const int PRE_TOT = 64 * 256 + 256 * 256 + 256 + 256 * 1024;
    precompute_k<<<(PRE_TOT + 255) / 256, 256>>>(kv_w, dot_w, head_w, head_b, q_w, q_b);
    k1_tc<<<dim3(HW / 64, NB), 256, C1_SMEM>>>(x);
    k2_window<<<dim3(4, 64, NB), 512>>>();
    k3_mma<<<dim3(NCOLS / 128, 2, 1), 256, K3_SMEM>>>(out);
}

// round 16
// speedup vs baseline: 1.1951x; 1.1951x over previous
#include <cuda_runtime.h>
#include <cuda_bf16.h>
#include <cuda_fp16.h>
#include <cstdint>

// Problem constants
#define NB    4
#define NC    256
#define HW    4096
#define NCOLS 16384          // B*H*W
#define MW    320            // 64 attn channels + 256 hv channels

// -------- persistent device scratch (allocation-free rule) --------
__device__ float g_constz[NC];                            // folded bias [256]
__device__ float g_G[(size_t)MW * NCOLS];                 // stage1: rows 0..63 = exp(attn), rows 64.. = hv
__device__ __nv_bfloat16 g_W1hi[MW * NC];                 // folded weights hi [320][256]
__device__ __nv_bfloat16 g_W1lo[MW * NC];                 // folded weights lo
__device__ __half g_Yh[(size_t)NCOLS * 1024];             // stage2 out, single fp16 [16384][1024]
__device__ __half g_QWhi[256 * 1024];                     // q_w fp16 hi
__device__ __half g_QWlo[256 * 1024];                     // q_w fp16 lo

// ======================= portable PTX helpers (sm_80+ ISA only) =======================
__device__ __forceinline__ uint32_t smem_u32(const void* p) {
    return (uint32_t)__cvta_generic_to_shared(p);
}
__device__ __forceinline__ void cp16(uint32_t s, const void* g) {
    asm volatile("cp.async.cg.shared.global [%0], [%1], 16;" :: "r"(s), "l"(g));
}
__device__ __forceinline__ void cp_commit() {
    asm volatile("cp.async.commit_group;" ::: "memory");
}
template <int N> __device__ __forceinline__ void cp_wait() {
    asm volatile("cp.async.wait_group %0;" :: "n"(N) : "memory");
}
__device__ __forceinline__ void ldm_x4(uint32_t a, uint32_t& r0, uint32_t& r1,
                                       uint32_t& r2, uint32_t& r3) {
    asm volatile("ldmatrix.sync.aligned.m8n8.x4.shared.b16 {%0,%1,%2,%3}, [%4];"
                 : "=r"(r0), "=r"(r1), "=r"(r2), "=r"(r3) : "r"(a));
}
__device__ __forceinline__ void mma16816(float* d, const uint32_t* a, const uint32_t* b) {
    asm volatile("mma.sync.aligned.m16n8k16.row.col.f32.bf16.bf16.f32 "
                 "{%0,%1,%2,%3}, {%4,%5,%6,%7}, {%8,%9}, {%0,%1,%2,%3};"
                 : "+f"(d[0]), "+f"(d[1]), "+f"(d[2]), "+f"(d[3])
                 : "r"(a[0]), "r"(a[1]), "r"(a[2]), "r"(a[3]), "r"(b[0]), "r"(b[1]));
}
__device__ __forceinline__ void mma16816h(float* d, const uint32_t* a, const uint32_t* b) {
    asm volatile("mma.sync.aligned.m16n8k16.row.col.f32.f16.f16.f32 "
                 "{%0,%1,%2,%3}, {%4,%5,%6,%7}, {%8,%9}, {%0,%1,%2,%3};"
                 : "+f"(d[0]), "+f"(d[1]), "+f"(d[2]), "+f"(d[3])
                 : "r"(a[0]), "r"(a[1]), "r"(a[2]), "r"(a[3]), "r"(b[0]), "r"(b[1]));
}

// ======================= precompute (tiny) =======================
__global__ void precompute_k(const float* __restrict__ kv_w,
                             const float* __restrict__ dot_w,
                             const float* __restrict__ head_w,
                             const float* __restrict__ head_b,
                             const float* __restrict__ q_w,
                             const float* __restrict__ q_b) {
    int i = blockIdx.x * blockDim.x + threadIdx.x;
    if (i < 64 * 256) {
        int m = i >> 8, c = i & 255;
        int n = m >> 4, q = m & 15;
        float s = 0.f;
        #pragma unroll 8
        for (int d = 0; d < 64; d++)
            s += dot_w[(n * 16 + q) * 64 + d] * kv_w[(n * 64 + d) * 256 + c];
        __nv_bfloat16 hi = __float2bfloat16(s);
        g_W1hi[m * 256 + c] = hi;
        g_W1lo[m * 256 + c] = __float2bfloat16(s - __bfloat162float(hi));
    } else if (i < 64 * 256 + 256 * 256) {
        int j = i - 64 * 256;
        int m = j >> 8, c = j & 255;
        int n = m >> 6, op = m & 63;
        float s = 0.f;
        #pragma unroll 8
        for (int d = 0; d < 64; d++)
            s += head_w[op * 256 + n * 64 + d] * kv_w[(256 + n * 64 + d) * 256 + c];
        __nv_bfloat16 hi = __float2bfloat16(s);
        g_W1hi[(64 + m) * 256 + c] = hi;
        g_W1lo[(64 + m) * 256 + c] = __float2bfloat16(s - __bfloat162float(hi));
    } else if (i < 64 * 256 + 256 * 256 + 256) {
        int o = i - (64 * 256 + 256 * 256);
        float s = q_b[o];
        for (int c = 0; c < 1024; c += 4) {
            float4 v = *reinterpret_cast<const float4*>(&q_w[o * 1024 + c]);
            int hb = c & 63;
            s += v.x * head_b[hb] + v.y * head_b[hb + 1]
               + v.z * head_b[hb + 2] + v.w * head_b[hb + 3];
        }
        g_constz[o] = s;
    } else if (i < 64 * 256 + 256 * 256 + 256 + 256 * 1024) {
        int j = i - (64 * 256 + 256 * 256 + 256);
        float v = q_w[j];
        __half hi = __float2half(v);
        g_QWhi[j] = hi;
        g_QWlo[j] = __float2half(v - __half2float(hi));
    }
}

// ======================= K1: tensor-core bf16-split GEMM + fused exp (proven R11) ==============
#define C1_RS    80
#define C1_AHI   0
#define C1_ALO   25600
#define C1_BHI   51200
#define C1_BLO   56320
#define C1_STG   61440
#define C1_SMEM  78848

__device__ __forceinline__ void k1_issueA(uint32_t sb, int k0, int t) {
    #pragma unroll
    for (int i = 0; i < 5; ++i) {
        int idx = t + i * 256;
        int row = idx >> 2, c = idx & 3;
        uint32_t so = row * C1_RS + c * 16;
        size_t go = (size_t)row * 256 + k0 + c * 8;
        cp16(sb + C1_AHI + so, g_W1hi + go);
        cp16(sb + C1_ALO + so, g_W1lo + go);
    }
}
__device__ __forceinline__ void k1_issueStg(uint32_t sb, int buf, const float* __restrict__ xb,
                                            int col0, int k0, int t) {
    #pragma unroll
    for (int i = 0; i < 2; ++i) {
        int idx = t + i * 256;
        int row = idx >> 4, c = idx & 15;
        cp16(sb + C1_STG + buf * 8704 + row * 272 + c * 16,
             xb + (size_t)(k0 + row) * HW + col0 + c * 4);
    }
}

__global__ void __launch_bounds__(256, 2) k1_tc(const float* __restrict__ x) {
    extern __shared__ __align__(128) char smem[];
    const uint32_t sb = smem_u32(smem);
    const int t = threadIdx.x, wid = t >> 5, lid = t & 31;
    const int col0 = blockIdx.x * 64;
    const int b    = blockIdx.y;
    const int wm = (wid & 3) * 80, wn = (wid >> 2) * 32;
    const float* xb = x + (size_t)b * NC * HW;

    float acc[20][4];
    #pragma unroll
    for (int i = 0; i < 20; i++) { acc[i][0] = acc[i][1] = acc[i][2] = acc[i][3] = 0.f; }

    k1_issueA(sb, 0, t);
    k1_issueStg(sb, 0, xb, col0, 0, t);
    cp_commit();

    const uint32_t a_off = (uint32_t)((lid & 15) * C1_RS + (lid >> 4) * 16);
    const int bn = (lid & 7) + ((lid >> 4) << 3);
    const uint32_t b_off = (uint32_t)(bn * C1_RS + ((lid >> 3) & 1) * 16);
    const int cn = t & 63, ckq = t >> 6;

    for (int c = 0; c < 8; ++c) {
        if (c < 7) {
            k1_issueStg(sb, (c + 1) & 1, xb, col0, (c + 1) * 32, t);
            cp_commit();
            cp_wait<1>();
        } else {
            cp_wait<0>();
        }
        __syncthreads();
        {   // convert fp32 staging [k][n] -> bf16 hi/lo [n][k]
            const float* stg = reinterpret_cast<const float*>(smem + C1_STG + (c & 1) * 8704);
            unsigned short hh[8], ll[8];
            #pragma unroll
            for (int j = 0; j < 8; ++j) {
                float f = stg[(ckq * 8 + j) * 68 + cn];
                __nv_bfloat16 hi = __float2bfloat16(f);
                __nv_bfloat16 lo = __float2bfloat16(f - __bfloat162float(hi));
                hh[j] = __bfloat16_as_ushort(hi);
                ll[j] = __bfloat16_as_ushort(lo);
            }
            uint32_t base = cn * C1_RS + ckq * 16;
            *reinterpret_cast<uint4*>(smem + C1_BHI + base) =
                make_uint4((uint32_t)hh[0] | ((uint32_t)hh[1] << 16),
                           (uint32_t)hh[2] | ((uint32_t)hh[3] << 16),
                           (uint32_t)hh[4] | ((uint32_t)hh[5] << 16),
                           (uint32_t)hh[6] | ((uint32_t)hh[7] << 16));
            *reinterpret_cast<uint4*>(smem + C1_BLO + base) =
                make_uint4((uint32_t)ll[0] | ((uint32_t)ll[1] << 16),
                           (uint32_t)ll[2] | ((uint32_t)ll[3] << 16),
                           (uint32_t)ll[4] | ((uint32_t)ll[5] << 16),
                           (uint32_t)ll[6] | ((uint32_t)ll[7] << 16));
        }
        __syncthreads();
        const uint32_t ahib = sb + C1_AHI + wm * C1_RS;
        const uint32_t alob = sb + C1_ALO + wm * C1_RS;
        const uint32_t bhib = sb + C1_BHI + wn * C1_RS;
        const uint32_t blob = sb + C1_BLO + wn * C1_RS;
        #pragma unroll
        for (int kk = 0; kk < 2; ++kk) {
            uint32_t kb = kk * 32;
            uint32_t bh[8], bl[8];
            #pragma unroll
            for (int nb = 0; nb < 2; ++nb) {
                ldm_x4(bhib + nb * 16 * C1_RS + b_off + kb,
                       bh[nb * 4], bh[nb * 4 + 1], bh[nb * 4 + 2], bh[nb * 4 + 3]);
                ldm_x4(blob + nb * 16 * C1_RS + b_off + kb,
                       bl[nb * 4], bl[nb * 4 + 1], bl[nb * 4 + 2], bl[nb * 4 + 3]);
            }
            #pragma unroll
            for (int mi = 0; mi < 5; ++mi) {
                uint32_t ah[4], al[4];
                ldm_x4(ahib + mi * 16 * C1_RS + a_off + kb, ah[0], ah[1], ah[2], ah[3]);
                ldm_x4(alob + mi * 16 * C1_RS + a_off + kb, al[0], al[1], al[2], al[3]);
                #pragma unroll
                for (int nj = 0; nj < 4; ++nj) {
                    mma16816(acc[mi * 4 + nj], ah, bh + nj * 2);   // hi*hi
                    mma16816(acc[mi * 4 + nj], al, bh + nj * 2);   // lo*hi
                    mma16816(acc[mi * 4 + nj], ah, bl + nj * 2);   // hi*lo
                }
            }
        }
        __syncthreads();
        if (c < 7) {
            k1_issueA(sb, (c + 1) * 32, t);
            cp_commit();
        }
    }

    const int bcol = b * HW;
    #pragma unroll
    for (int mi = 0; mi < 5; ++mi) {
        int row = wm + mi * 16 + (lid >> 2);
        #pragma unroll
        for (int nj = 0; nj < 4; ++nj) {
            int col = bcol + col0 + wn + nj * 8 + (lid & 3) * 2;
            float* a = acc[mi * 4 + nj];
            float v0 = a[0], v1 = a[1], v2 = a[2], v3 = a[3];
            if (row < 64)     { v0 = __expf(v0); v1 = __expf(v1); }
            if (row + 8 < 64) { v2 = __expf(v2); v3 = __expf(v3); }
            *reinterpret_cast<float2*>(&g_G[(size_t)row * NCOLS + col]) = make_float2(v0, v1);
            *reinterpret_cast<float2*>(&g_G[(size_t)(row + 8) * NCOLS + col]) = make_float2(v2, v3);
        }
    }
}

// ======================= K2: windowed softmax (exp precomputed) + aggregation (R11) ============
__global__ void __launch_bounds__(512) k2_window() {
    __shared__ float sE[16][56];        // exp(logits): q x 54 positions, halo = exp(0) = 1
    __shared__ float sHV[64][56];
    __shared__ float sSM[16][16][9];

    int t  = threadIdx.x;
    int w0 = blockIdx.x * 16;
    int h  = blockIdx.y;
    int b  = blockIdx.z;
    int bcol = b * HW;
    int px = t >> 5;
    int oh = t & 31;

    float acc0[16], acc1[16];
    #pragma unroll
    for (int q = 0; q < 16; q++) { acc0[q] = 0.f; acc1[q] = 0.f; }

    for (int n = 0; n < 4; n++) {
        __syncthreads();
        for (int i = t; i < 864; i += 512) {
            int q = i / 54, pos = i % 54;
            int r = pos / 18, cc = pos % 18;
            int gh = h - 1 + r, gw = w0 - 1 + cc;
            float v = 1.0f;                                   // exp(0) for padded logits
            if (gh >= 0 && gh < 64 && gw >= 0 && gw < 64)
                v = g_G[(size_t)(n * 16 + q) * NCOLS + bcol + gh * 64 + gw];
            sE[q][pos] = v;
        }
        for (int i = t; i < 3456; i += 512) {
            int ch = i / 54, pos = i % 54;
            int r = pos / 18, cc = pos % 18;
            int gh = h - 1 + r, gw = w0 - 1 + cc;
            float v = 0.f;
            if (gh >= 0 && gh < 64 && gw >= 0 && gw < 64)
                v = g_G[(size_t)(64 + n * 64 + ch) * NCOLS + bcol + gh * 64 + gw];
            sHV[ch][pos] = v;
        }
        __syncthreads();
        if (t < 256) {
            int p2 = t >> 4, q = t & 15;
            float e[9], s = 0.f;
            #pragma unroll
            for (int r = 0; r < 3; r++)
                #pragma unroll
                for (int dc = 0; dc < 3; dc++) {
                    float v = sE[q][r * 18 + p2 + dc];
                    e[r * 3 + dc] = v; s += v;
                }
            float rs = 1.0f / s;
            #pragma unroll
            for (int l = 0; l < 9; l++) sSM[p2][q][l] = e[l] * rs;
        }
        __syncthreads();
        float hv0[9], hv1[9];
        #pragma unroll
        for (int r = 0; r < 3; r++)
            #pragma unroll
            for (int dc = 0; dc < 3; dc++) {
                int pos = r * 18 + px + dc;
                hv0[r * 3 + dc] = sHV[oh][pos];
                hv1[r * 3 + dc] = sHV[oh + 32][pos];
            }
        #pragma unroll
        for (int q = 0; q < 16; q++) {
            #pragma unroll
            for (int l = 0; l < 9; l++) {
                float s = sSM[px][q][l];
                acc0[q] += s * hv0[l];
                acc1[q] += s * hv1[l];
            }
        }
    }
    // write Y as single fp16: [col][q*64 + o']
    size_t col = (size_t)bcol + h * 64 + w0 + px;
    __half* yh = g_Yh + col * 1024 + oh;
    #pragma unroll
    for (int q = 0; q < 16; q++) {
        yh[q * 64]      = __float2half(acc0[q]);
        yh[q * 64 + 32] = __float2half(acc1[q]);
    }
}

// ======================= K3: mma.sync fp16 2-term GEMM =======================
// Z[256,16384] = Qw[256,1024] @ Y^T, fp16: Ahi*B + Alo*B (A = q_w split, B = Y single fp16).
// CTA tile 128x128, warp tile 32x64, K-step 32, cp.async 2-stage. 30KB/stage.
#define K3_RS    80
#define K3_TILE  10240
#define K3_AHI   0
#define K3_ALO   10240
#define K3_BHI   20480
#define K3_STAGE 30720
#define K3_SMEM  61440

__device__ __forceinline__ void k3_issue(uint32_t sbuf,
                                         const __half* __restrict__ A0,
                                         const __half* __restrict__ A1,
                                         const __half* __restrict__ B0,
                                         int k0, int t) {
    int r = t >> 2, c = t & 3;
    #pragma unroll
    for (int half = 0; half < 2; ++half) {
        int row = r + half * 64;
        uint32_t so = row * K3_RS + c * 16;
        size_t go = (size_t)row * 1024 + k0 + c * 8;
        cp16(sbuf + K3_AHI + so, A0 + go);
        cp16(sbuf + K3_ALO + so, A1 + go);
        cp16(sbuf + K3_BHI + so, B0 + go);
    }
}

__global__ void __launch_bounds__(256, 2) k3_mma(float* __restrict__ out) {
    extern __shared__ __align__(128) char smem[];
    const uint32_t sb = smem_u32(smem);
    const int t = threadIdx.x, wid = t >> 5, lid = t & 31;
    const int m0 = blockIdx.y * 128, n0 = blockIdx.x * 128;
    const int wm = (wid & 3) * 32, wn = (wid >> 2) * 64;

    const __half* Ah = g_QWhi + (size_t)m0 * 1024;
    const __half* Al = g_QWlo + (size_t)m0 * 1024;
    const __half* Bh = g_Yh + (size_t)n0 * 1024;

    float acc[16][4];
    #pragma unroll
    for (int i = 0; i < 16; i++) { acc[i][0] = acc[i][1] = acc[i][2] = acc[i][3] = 0.f; }

    k3_issue(sb, Ah, Al, Bh, 0, t);
    cp_commit();

    const uint32_t a_off = (uint32_t)((lid & 15) * K3_RS + (lid >> 4) * 16);
    const int bn = (lid & 7) + ((lid >> 4) << 3);
    const uint32_t b_off = (uint32_t)(bn * K3_RS + ((lid >> 3) & 1) * 16);

    for (int cs = 0; cs < 32; ++cs) {
        if (cs < 31) {
            k3_issue(sb + ((cs + 1) & 1) * K3_STAGE, Ah, Al, Bh, (cs + 1) * 32, t);
            cp_commit();
            cp_wait<1>();
        } else {
            cp_wait<0>();
        }
        __syncthreads();
        uint32_t buf   = sb + (cs & 1) * K3_STAGE;
        uint32_t abase = buf + K3_AHI + wm * K3_RS;
        uint32_t lbase = buf + K3_ALO + wm * K3_RS;
        uint32_t bbase = buf + K3_BHI + wn * K3_RS;
        #pragma unroll
        for (int kk = 0; kk < 2; ++kk) {
            uint32_t kb = kk * 32;
            uint32_t ah[8], al[8], bb[16];
            ldm_x4(abase + a_off + kb,                ah[0], ah[1], ah[2], ah[3]);
            ldm_x4(abase + 16 * K3_RS + a_off + kb,   ah[4], ah[5], ah[6], ah[7]);
            ldm_x4(lbase + a_off + kb,                al[0], al[1], al[2], al[3]);
            ldm_x4(lbase + 16 * K3_RS + a_off + kb,   al[4], al[5], al[6], al[7]);
            #pragma unroll
            for (int nb = 0; nb < 4; ++nb)
                ldm_x4(bbase + nb * 16 * K3_RS + b_off + kb,
                       bb[nb * 4], bb[nb * 4 + 1], bb[nb * 4 + 2], bb[nb * 4 + 3]);
            #pragma unroll
            for (int mi = 0; mi < 2; ++mi)
                #pragma unroll
                for (int nj = 0; nj < 8; ++nj) {
                    mma16816h(acc[mi * 8 + nj], ah + mi * 4, bb + nj * 2);   // hi*B
                    mma16816h(acc[mi * 8 + nj], al + mi * 4, bb + nj * 2);   // lo*B
                }
        }
        __syncthreads();
    }

    const int bidx = blockIdx.x >> 5;
    const int hwb  = ((blockIdx.x & 31) * 128) + wn + (lid & 3) * 2;
    #pragma unroll
    for (int mi = 0; mi < 2; ++mi) {
        int row = m0 + wm + mi * 16 + (lid >> 2);
        float cz0 = g_constz[row], cz1 = g_constz[row + 8];
        float* p0 = out + (size_t)bidx * 1048576 + (size_t)row * 4096 + hwb;
        float* p1 = p0 + 8 * 4096;
        #pragma unroll
        for (int nj = 0; nj < 8; ++nj) {
            float* a = acc[mi * 8 + nj];
            *reinterpret_cast<float2*>(p0 + nj * 8) = make_float2(a[0] + cz0, a[1] + cz0);
            *reinterpret_cast<float2*>(p1 + nj * 8) = make_float2(a[2] + cz1, a[3] + cz1);
        }
    }
}

// ======================= launch =======================
extern "C" void kernel_launch(void* const* d_in, const int* in_sizes, int n_in,
                              void* d_out, int out_size) {
    (void)in_sizes; (void)n_in; (void)out_size;
    const float* x      = (const float*)d_in[0];
    const float* kv_w   = (const float*)d_in[1];
    const float* dot_w  = (const float*)d_in[2];
    const float* head_w = (const float*)d_in[3];
    const float* head_b = (const float*)d_in[4];
    const float* q_w    = (const float*)d_in[5];
    const float* q_b    = (const float*)d_in[6];
    float* out = (float*)d_out;

    cudaFuncSetAttribute(k1_tc,  cudaFuncAttributeMaxDynamicSharedMemorySize, C1_SMEM);
    cudaFuncSetAttribute(k3_mma, cudaFuncAttributeMaxDynamicSharedMemorySize, K3_SMEM);

    const int PRE_TOT = 64 * 256 + 256 * 256 + 256 + 256 * 1024;
    precompute_k<<<(PRE_TOT + 255) / 256, 256>>>(kv_w, dot_w, head_w, head_b, q_w, q_b);
    k1_tc<<<dim3(HW / 64, NB), 256, C1_SMEM>>>(x);
    k2_window<<<dim3(4, 64, NB), 512>>>();
    k3_mma<<<dim3(NCOLS / 128, 2, 1), 256, K3_SMEM>>>(out);
}

// round 17
// speedup vs baseline: 1.5149x; 1.2676x over previous
#include <cuda_runtime.h>
#include <cuda_fp16.h>
#include <cstdint>

// Problem constants
#define NB    4
#define NC    256
#define HW    4096
#define NCOLS 16384          // B*H*W
#define MW    320            // 64 attn channels + 256 hv channels

// -------- persistent device scratch (allocation-free rule) --------
__device__ float g_constz[NC];                            // folded bias [256]
__device__ float g_G[(size_t)MW * NCOLS];                 // stage1: rows 0..63 = exp(attn), rows 64.. = hv
__device__ __half g_W1hi[MW * NC];                        // folded weights fp16 hi [320][256]
__device__ __half g_W1lo[MW * NC];                        // folded weights fp16 lo
__device__ __half g_Yh[(size_t)NCOLS * 1024];             // stage2 out, single fp16 [16384][1024]
__device__ __half g_QWhi[256 * 1024];                     // q_w fp16 hi
__device__ __half g_QWlo[256 * 1024];                     // q_w fp16 lo

// ======================= portable PTX helpers (sm_80+ ISA only) =======================
__device__ __forceinline__ uint32_t smem_u32(const void* p) {
    return (uint32_t)__cvta_generic_to_shared(p);
}
__device__ __forceinline__ void cp16(uint32_t s, const void* g) {
    asm volatile("cp.async.cg.shared.global [%0], [%1], 16;" :: "r"(s), "l"(g));
}
__device__ __forceinline__ void cp_commit() {
    asm volatile("cp.async.commit_group;" ::: "memory");
}
template <int N> __device__ __forceinline__ void cp_wait() {
    asm volatile("cp.async.wait_group %0;" :: "n"(N) : "memory");
}
__device__ __forceinline__ void ldm_x4(uint32_t a, uint32_t& r0, uint32_t& r1,
                                       uint32_t& r2, uint32_t& r3) {
    asm volatile("ldmatrix.sync.aligned.m8n8.x4.shared.b16 {%0,%1,%2,%3}, [%4];"
                 : "=r"(r0), "=r"(r1), "=r"(r2), "=r"(r3) : "r"(a));
}
__device__ __forceinline__ void mma16816h(float* d, const uint32_t* a, const uint32_t* b) {
    asm volatile("mma.sync.aligned.m16n8k16.row.col.f32.f16.f16.f32 "
                 "{%0,%1,%2,%3}, {%4,%5,%6,%7}, {%8,%9}, {%0,%1,%2,%3};"
                 : "+f"(d[0]), "+f"(d[1]), "+f"(d[2]), "+f"(d[3])
                 : "r"(a[0]), "r"(a[1]), "r"(a[2]), "r"(a[3]), "r"(b[0]), "r"(b[1]));
}

// ======================= precompute (tiny) =======================
__global__ void precompute_k(const float* __restrict__ kv_w,
                             const float* __restrict__ dot_w,
                             const float* __restrict__ head_w,
                             const float* __restrict__ head_b,
                             const float* __restrict__ q_w,
                             const float* __restrict__ q_b) {
    int i = blockIdx.x * blockDim.x + threadIdx.x;
    if (i < 64 * 256) {
        int m = i >> 8, c = i & 255;
        int n = m >> 4, q = m & 15;
        float s = 0.f;
        #pragma unroll 8
        for (int d = 0; d < 64; d++)
            s += dot_w[(n * 16 + q) * 64 + d] * kv_w[(n * 64 + d) * 256 + c];
        __half hi = __float2half(s);
        g_W1hi[m * 256 + c] = hi;
        g_W1lo[m * 256 + c] = __float2half(s - __half2float(hi));
    } else if (i < 64 * 256 + 256 * 256) {
        int j = i - 64 * 256;
        int m = j >> 8, c = j & 255;
        int n = m >> 6, op = m & 63;
        float s = 0.f;
        #pragma unroll 8
        for (int d = 0; d < 64; d++)
            s += head_w[op * 256 + n * 64 + d] * kv_w[(256 + n * 64 + d) * 256 + c];
        __half hi = __float2half(s);
        g_W1hi[(64 + m) * 256 + c] = hi;
        g_W1lo[(64 + m) * 256 + c] = __float2half(s - __half2float(hi));
    } else if (i < 64 * 256 + 256 * 256 + 256) {
        int o = i - (64 * 256 + 256 * 256);
        float s = q_b[o];
        for (int c = 0; c < 1024; c += 4) {
            float4 v = *reinterpret_cast<const float4*>(&q_w[o * 1024 + c]);
            int hb = c & 63;
            s += v.x * head_b[hb] + v.y * head_b[hb + 1]
               + v.z * head_b[hb + 2] + v.w * head_b[hb + 3];
        }
        g_constz[o] = s;
    } else if (i < 64 * 256 + 256 * 256 + 256 + 256 * 1024) {
        int j = i - (64 * 256 + 256 * 256 + 256);
        float v = q_w[j];
        __half hi = __float2half(v);
        g_QWhi[j] = hi;
        g_QWlo[j] = __float2half(v - __half2float(hi));
    }
}

// ======================= K1: fp16 2-term tensor-core GEMM + fused exp =======================
// G[320, 16384] = W1[320,256] @ X[256, hw] per batch; rows < 64 store exp(logit).
// W1 split fp16 hi/lo; x single fp16. A single-buffered; x staging double-buffered.
#define C1_RS    80
#define C1_AHI   0          // 320*80 = 25600
#define C1_ALO   25600
#define C1_BH    51200      // 64*80 = 5120
#define C1_STG   56320      // 2 x 8704 fp32 staging
#define C1_SMEM  73728

__device__ __forceinline__ void k1_issueA(uint32_t sb, int k0, int t) {
    #pragma unroll
    for (int i = 0; i < 5; ++i) {
        int idx = t + i * 256;
        int row = idx >> 2, c = idx & 3;
        uint32_t so = row * C1_RS + c * 16;
        size_t go = (size_t)row * 256 + k0 + c * 8;
        cp16(sb + C1_AHI + so, g_W1hi + go);
        cp16(sb + C1_ALO + so, g_W1lo + go);
    }
}
__device__ __forceinline__ void k1_issueStg(uint32_t sb, int buf, const float* __restrict__ xb,
                                            int col0, int k0, int t) {
    #pragma unroll
    for (int i = 0; i < 2; ++i) {
        int idx = t + i * 256;
        int row = idx >> 4, c = idx & 15;
        cp16(sb + C1_STG + buf * 8704 + row * 272 + c * 16,
             xb + (size_t)(k0 + row) * HW + col0 + c * 4);
    }
}

__global__ void __launch_bounds__(256, 2) k1_tc(const float* __restrict__ x) {
    extern __shared__ __align__(128) char smem[];
    const uint32_t sb = smem_u32(smem);
    const int t = threadIdx.x, wid = t >> 5, lid = t & 31;
    const int col0 = blockIdx.x * 64;
    const int b    = blockIdx.y;
    const int wm = (wid & 3) * 80, wn = (wid >> 2) * 32;
    const float* xb = x + (size_t)b * NC * HW;

    float acc[20][4];
    #pragma unroll
    for (int i = 0; i < 20; i++) { acc[i][0] = acc[i][1] = acc[i][2] = acc[i][3] = 0.f; }

    k1_issueA(sb, 0, t);
    k1_issueStg(sb, 0, xb, col0, 0, t);
    cp_commit();

    const uint32_t a_off = (uint32_t)((lid & 15) * C1_RS + (lid >> 4) * 16);
    const int bn = (lid & 7) + ((lid >> 4) << 3);
    const uint32_t b_off = (uint32_t)(bn * C1_RS + ((lid >> 3) & 1) * 16);
    const int cn = t & 63, ckq = t >> 6;

    for (int c = 0; c < 8; ++c) {
        if (c < 7) {
            k1_issueStg(sb, (c + 1) & 1, xb, col0, (c + 1) * 32, t);
            cp_commit();
            cp_wait<1>();
        } else {
            cp_wait<0>();
        }
        __syncthreads();
        {   // convert fp32 staging [k][n] -> single fp16 [n][k]
            const float* stg = reinterpret_cast<const float*>(smem + C1_STG + (c & 1) * 8704);
            unsigned short hh[8];
            #pragma unroll
            for (int j = 0; j < 8; ++j) {
                float f = stg[(ckq * 8 + j) * 68 + cn];
                hh[j] = __half_as_ushort(__float2half(f));
            }
            uint32_t base = cn * C1_RS + ckq * 16;
            *reinterpret_cast<uint4*>(smem + C1_BH + base) =
                make_uint4((uint32_t)hh[0] | ((uint32_t)hh[1] << 16),
                           (uint32_t)hh[2] | ((uint32_t)hh[3] << 16),
                           (uint32_t)hh[4] | ((uint32_t)hh[5] << 16),
                           (uint32_t)hh[6] | ((uint32_t)hh[7] << 16));
        }
        __syncthreads();
        const uint32_t ahib = sb + C1_AHI + wm * C1_RS;
        const uint32_t alob = sb + C1_ALO + wm * C1_RS;
        const uint32_t bhib = sb + C1_BH + wn * C1_RS;
        #pragma unroll
        for (int kk = 0; kk < 2; ++kk) {
            uint32_t kb = kk * 32;
            uint32_t bh[8];
            #pragma unroll
            for (int nb = 0; nb < 2; ++nb)
                ldm_x4(bhib + nb * 16 * C1_RS + b_off + kb,
                       bh[nb * 4], bh[nb * 4 + 1], bh[nb * 4 + 2], bh[nb * 4 + 3]);
            #pragma unroll
            for (int mi = 0; mi < 5; ++mi) {
                uint32_t ah[4], al[4];
                ldm_x4(ahib + mi * 16 * C1_RS + a_off + kb, ah[0], ah[1], ah[2], ah[3]);
                ldm_x4(alob + mi * 16 * C1_RS + a_off + kb, al[0], al[1], al[2], al[3]);
                #pragma unroll
                for (int nj = 0; nj < 4; ++nj) {
                    mma16816h(acc[mi * 4 + nj], ah, bh + nj * 2);   // hi*B
                    mma16816h(acc[mi * 4 + nj], al, bh + nj * 2);   // lo*B
                }
            }
        }
        __syncthreads();
        if (c < 7) {
            k1_issueA(sb, (c + 1) * 32, t);
            cp_commit();
        }
    }

    const int bcol = b * HW;
    #pragma unroll
    for (int mi = 0; mi < 5; ++mi) {
        int row = wm + mi * 16 + (lid >> 2);
        #pragma unroll
        for (int nj = 0; nj < 4; ++nj) {
            int col = bcol + col0 + wn + nj * 8 + (lid & 3) * 2;
            float* a = acc[mi * 4 + nj];
            float v0 = a[0], v1 = a[1], v2 = a[2], v3 = a[3];
            if (row < 64)     { v0 = __expf(v0); v1 = __expf(v1); }
            if (row + 8 < 64) { v2 = __expf(v2); v3 = __expf(v3); }
            *reinterpret_cast<float2*>(&g_G[(size_t)row * NCOLS + col]) = make_float2(v0, v1);
            *reinterpret_cast<float2*>(&g_G[(size_t)(row + 8) * NCOLS + col]) = make_float2(v2, v3);
        }
    }
}

// ======================= K2: windowed softmax + aggregation (2 blocks/SM) =======================
// 8 px/block, 512 threads: px = t>>6, oh = t&63 (ONE channel/thread -> 16 accs, ~45 regs).
// sSM l-dim padded to 12 -> float4 reads (48 LDS vs 144 per head).
__global__ void __launch_bounds__(512, 2) k2_window() {
    __shared__ float sE[16][33];        // 16q x 30 pos (3r x 10c), halo = exp(0) = 1
    __shared__ float sHV[64][33];
    __shared__ float sSM[8][16][12];

    int t  = threadIdx.x;
    int w0 = blockIdx.x * 8;
    int h  = blockIdx.y;
    int b  = blockIdx.z;
    int bcol = b * HW;
    int px = t >> 6;
    int oh = t & 63;

    float acc[16];
    #pragma unroll
    for (int q = 0; q < 16; q++) acc[q] = 0.f;

    for (int n = 0; n < 4; n++) {
        __syncthreads();
        if (t < 480) {
            int q = t / 30, pos = t % 30;
            int r = pos / 10, cc = pos % 10;
            int gh = h - 1 + r, gw = w0 - 1 + cc;
            float v = 1.0f;                                   // exp(0) for padded logits
            if (gh >= 0 && gh < 64 && gw >= 0 && gw < 64)
                v = g_G[(size_t)(n * 16 + q) * NCOLS + bcol + gh * 64 + gw];
            sE[q][pos] = v;
        }
        for (int i = t; i < 1920; i += 512) {
            int ch = i / 30, pos = i % 30;
            int r = pos / 10, cc = pos % 10;
            int gh = h - 1 + r, gw = w0 - 1 + cc;
            float v = 0.f;
            if (gh >= 0 && gh < 64 && gw >= 0 && gw < 64)
                v = g_G[(size_t)(64 + n * 64 + ch) * NCOLS + bcol + gh * 64 + gw];
            sHV[ch][pos] = v;
        }
        __syncthreads();
        if (t < 128) {
            int p2 = t >> 4, q = t & 15;
            float e[9], s = 0.f;
            #pragma unroll
            for (int r = 0; r < 3; r++)
                #pragma unroll
                for (int dc = 0; dc < 3; dc++) {
                    float v = sE[q][r * 10 + p2 + dc];
                    e[r * 3 + dc] = v; s += v;
                }
            float rs = 1.0f / s;
            #pragma unroll
            for (int l = 0; l < 9; l++) sSM[p2][q][l] = e[l] * rs;
        }
        __syncthreads();
        float hv[9];
        #pragma unroll
        for (int r = 0; r < 3; r++)
            #pragma unroll
            for (int dc = 0; dc < 3; dc++)
                hv[r * 3 + dc] = sHV[oh][r * 10 + px + dc];
        #pragma unroll
        for (int q = 0; q < 16; q++) {
            float4 s0 = *reinterpret_cast<float4*>(&sSM[px][q][0]);
            float4 s1 = *reinterpret_cast<float4*>(&sSM[px][q][4]);
            float s8 = sSM[px][q][8];
            acc[q] += s0.x * hv[0] + s0.y * hv[1] + s0.z * hv[2] + s0.w * hv[3]
                    + s1.x * hv[4] + s1.y * hv[5] + s1.z * hv[6] + s1.w * hv[7]
                    + s8 * hv[8];
        }
    }
    // write Y as single fp16: [col][q*64 + oh]
    size_t col = (size_t)bcol + h * 64 + w0 + px;
    __half* yh = g_Yh + col * 1024 + oh;
    #pragma unroll
    for (int q = 0; q < 16; q++)
        yh[q * 64] = __float2half(acc[q]);
}

// ======================= K3: mma.sync fp16 2-term GEMM (proven, 66us) =======================
#define K3_RS    80
#define K3_TILE  10240
#define K3_AHI   0
#define K3_ALO   10240
#define K3_BHI   20480
#define K3_STAGE 30720
#define K3_SMEM  61440

__device__ __forceinline__ void k3_issue(uint32_t sbuf,
                                         const __half* __restrict__ A0,
                                         const __half* __restrict__ A1,
                                         const __half* __restrict__ B0,
                                         int k0, int t) {
    int r = t >> 2, c = t & 3;
    #pragma unroll
    for (int half = 0; half < 2; ++half) {
        int row = r + half * 64;
        uint32_t so = row * K3_RS + c * 16;
        size_t go = (size_t)row * 1024 + k0 + c * 8;
        cp16(sbuf + K3_AHI + so, A0 + go);
        cp16(sbuf + K3_ALO + so, A1 + go);
        cp16(sbuf + K3_BHI + so, B0 + go);
    }
}

__global__ void __launch_bounds__(256, 2) k3_mma(float* __restrict__ out) {
    extern __shared__ __align__(128) char smem[];
    const uint32_t sb = smem_u32(smem);
    const int t = threadIdx.x, wid = t >> 5, lid = t & 31;
    const int m0 = blockIdx.y * 128, n0 = blockIdx.x * 128;
    const int wm = (wid & 3) * 32, wn = (wid >> 2) * 64;

    const __half* Ah = g_QWhi + (size_t)m0 * 1024;
    const __half* Al = g_QWlo + (size_t)m0 * 1024;
    const __half* Bh = g_Yh + (size_t)n0 * 1024;

    float acc[16][4];
    #pragma unroll
    for (int i = 0; i < 16; i++) { acc[i][0] = acc[i][1] = acc[i][2] = acc[i][3] = 0.f; }

    k3_issue(sb, Ah, Al, Bh, 0, t);
    cp_commit();

    const uint32_t a_off = (uint32_t)((lid & 15) * K3_RS + (lid >> 4) * 16);
    const int bn = (lid & 7) + ((lid >> 4) << 3);
    const uint32_t b_off = (uint32_t)(bn * K3_RS + ((lid >> 3) & 1) * 16);

    for (int cs = 0; cs < 32; ++cs) {
        if (cs < 31) {
            k3_issue(sb + ((cs + 1) & 1) * K3_STAGE, Ah, Al, Bh, (cs + 1) * 32, t);
            cp_commit();
            cp_wait<1>();
        } else {
            cp_wait<0>();
        }
        __syncthreads();
        uint32_t buf   = sb + (cs & 1) * K3_STAGE;
        uint32_t abase = buf + K3_AHI + wm * K3_RS;
        uint32_t lbase = buf + K3_ALO + wm * K3_RS;
        uint32_t bbase = buf + K3_BHI + wn * K3_RS;
        #pragma unroll
        for (int kk = 0; kk < 2; ++kk) {
            uint32_t kb = kk * 32;
            uint32_t ah[8], al[8], bb[16];
            ldm_x4(abase + a_off + kb,                ah[0], ah[1], ah[2], ah[3]);
            ldm_x4(abase + 16 * K3_RS + a_off + kb,   ah[4], ah[5], ah[6], ah[7]);
            ldm_x4(lbase + a_off + kb,                al[0], al[1], al[2], al[3]);
            ldm_x4(lbase + 16 * K3_RS + a_off + kb,   al[4], al[5], al[6], al[7]);
            #pragma unroll
            for (int nb = 0; nb < 4; ++nb)
                ldm_x4(bbase + nb * 16 * K3_RS + b_off + kb,
                       bb[nb * 4], bb[nb * 4 + 1], bb[nb * 4 + 2], bb[nb * 4 + 3]);
            #pragma unroll
            for (int mi = 0; mi < 2; ++mi)
                #pragma unroll
                for (int nj = 0; nj < 8; ++nj) {
                    mma16816h(acc[mi * 8 + nj], ah + mi * 4, bb + nj * 2);   // hi*B
                    mma16816h(acc[mi * 8 + nj], al + mi * 4, bb + nj * 2);   // lo*B
                }
        }
        __syncthreads();
    }

    const int bidx = blockIdx.x >> 5;
    const int hwb  = ((blockIdx.x & 31) * 128) + wn + (lid & 3) * 2;
    #pragma unroll
    for (int mi = 0; mi < 2; ++mi) {
        int row = m0 + wm + mi * 16 + (lid >> 2);
        float cz0 = g_constz[row], cz1 = g_constz[row + 8];
        float* p0 = out + (size_t)bidx * 1048576 + (size_t)row * 4096 + hwb;
        float* p1 = p0 + 8 * 4096;
        #pragma unroll
        for (int nj = 0; nj < 8; ++nj) {
            float* a = acc[mi * 8 + nj];
            *reinterpret_cast<float2*>(p0 + nj * 8) = make_float2(a[0] + cz0, a[1] + cz0);
            *reinterpret_cast<float2*>(p1 + nj * 8) = make_float2(a[2] + cz1, a[3] + cz1);
        }
    }
}

// ======================= launch =======================
extern "C" void kernel_launch(void* const* d_in, const int* in_sizes, int n_in,
                              void* d_out, int out_size) {
    (void)in_sizes; (void)n_in; (void)out_size;
    const float* x      = (const float*)d_in[0];
    const float* kv_w   = (const float*)d_in[1];
    const float* dot_w  = (const float*)d_in[2];
    const float* head_w = (const float*)d_in[3];
    const float* head_b = (const float*)d_in[4];
    const float* q_w    = (const float*)d_in[5];
    const float* q_b    = (const float*)d_in[6];
    float* out = (float*)d_out;

    cudaFuncSetAttribute(k1_tc,  cudaFuncAttributeMaxDynamicSharedMemorySize, C1_SMEM);
    cudaFuncSetAttribute(k3_mma, cudaFuncAttributeMaxDynamicSharedMemorySize, K3_SMEM);

    const int PRE_TOT = 64 * 256 + 256 * 256 + 256 + 256 * 1024;
    precompute_k<<<(PRE_TOT + 255) / 256, 256>>>(kv_w, dot_w, head_w, head_b, q_w, q_b);
    k1_tc<<<dim3(HW / 64, NB), 256, C1_SMEM>>>(x);
    k2_window<<<dim3(8, 64, NB), 512>>>();
    k3_mma<<<dim3(NCOLS / 128, 2, 1), 256, K3_SMEM>>>(out);
}